// round 4
// baseline (speedup 1.0000x reference)
#include <cuda_runtime.h>
#include <cuda_bf16.h>
#include <math.h>

#define N 8192
#define NSEG 8
#define SEG 1024
#define T2 128
#define NUM_CHUNKS 8
#define STRIDE 6144
#define TOTAL 51200
#define FADE 1228

// -------- device scratch (no allocations allowed) --------
__device__ float g_S[NUM_CHUNKS][N * 3];          // smoothed chunks
__device__ float g_SM[N * 3];                     // sm output of current step
__device__ unsigned long long g_pkey[NSEG * N];   // partial argmin keys
__device__ int g_mi[N];                           // argmin indices
__device__ int g_best[N];                         // scatter last-wins (monotone across steps)

// -------- init: S[0] = chunks[0], best = -1 (reset EVERY call: determinism) ----
__global__ void k_init(const float* __restrict__ chunks) {
    int i = blockIdx.x * blockDim.x + threadIdx.x;
    if (i < N * 3) g_S[0][i] = chunks[i];
    if (i < N) g_best[i] = -1;
}

// -------- K1: partial argmin, replicating reference d2 rounding exactly --------
// Reference: d2 = (pp[:,None] + cc[None,:]) - 2.0 * (p @ c.T)
//   pp/cc: separately-rounded squares, left-to-right adds
//   dot:   SIMT GEMM ascending-k FMA chain starting from 0 (cublas/Triton style)
//   d2:    ((pp + cc) - (2*dot)), each elementwise op rounded
__global__ __launch_bounds__(256) void k_argmin(const float* __restrict__ C, int step) {
    __shared__ float4 sc[SEG];   // {cx, cy, cz, cc}
    const float* P = g_S[step - 1];
    int seg = blockIdx.y;

    for (int idx = threadIdx.x; idx < SEG; idx += blockDim.x) {
        int gj = seg * SEG + idx;
        float cx = C[gj * 3], cy = C[gj * 3 + 1], cz = C[gj * 3 + 2];
        float cc = __fadd_rn(__fadd_rn(__fmul_rn(cx, cx), __fmul_rn(cy, cy)),
                             __fmul_rn(cz, cz));
        sc[idx] = make_float4(cx, cy, cz, cc);
    }
    __syncthreads();

    int p = blockIdx.x * blockDim.x + threadIdx.x;
    float px = P[p * 3], py = P[p * 3 + 1], pz = P[p * 3 + 2];
    float pp = __fadd_rn(__fadd_rn(__fmul_rn(px, px), __fmul_rn(py, py)),
                         __fmul_rn(pz, pz));

    float best = __int_as_float(0x7f800000);  // +inf
    int bj = 0;

#pragma unroll 4
    for (int j = 0; j < SEG; j++) {
        float4 c = sc[j];
        // ascending-k FMA accumulation from 0 (SIMT GEMM semantics)
        float dot = __fmaf_rn(pz, c.z,
                    __fmaf_rn(py, c.y,
                    __fmaf_rn(px, c.x, 0.0f)));
        float d2 = __fsub_rn(__fadd_rn(pp, c.w), __fmul_rn(2.0f, dot));
        if (d2 < best) { best = d2; bj = j; }  // strict < keeps lowest j
    }

    unsigned int b = __float_as_uint(best);
    b = (b & 0x80000000u) ? ~b : (b | 0x80000000u);  // order-preserving transform
    g_pkey[seg * N + p] =
        ((unsigned long long)b << 32) | (unsigned int)(seg * SEG + bj);
}

// -------- K2: reduce argmin + fused (MLP mix) + 3 conv layers, halo-6 tiles --------
__global__ __launch_bounds__(256) void k_fuse_conv(
    const float* __restrict__ C, int step,
    const float* __restrict__ bw1, const float* __restrict__ bb1,
    const float* __restrict__ bw2, const float* __restrict__ bb2,
    const float* __restrict__ bw3, const float* __restrict__ bb3,
    const float* __restrict__ pw1, const float* __restrict__ pb1,
    const float* __restrict__ pw2, const float* __restrict__ pb2,
    const float* __restrict__ pw3, const float* __restrict__ pb3) {
    __shared__ float fs[3][T2 + 12];
    __shared__ float h1[32][T2 + 12];
    __shared__ float h2[32][T2 + 12];

    int t0 = blockIdx.x * T2;
    const float* P = g_S[step - 1];

    // phase 0: reduce partial argmin, compute fused for tile + halo(6)
    for (int l = threadIdx.x; l < T2 + 12; l += blockDim.x) {
        int g = t0 - 6 + l;
        float f0 = 0.f, f1 = 0.f, f2 = 0.f;
        if (g >= 0 && g < N) {
            unsigned long long k = g_pkey[g];
#pragma unroll
            for (int s = 1; s < NSEG; s++) {
                unsigned long long v = g_pkey[s * N + g];
                if (v < k) k = v;
            }
            int mi = (int)(unsigned int)(k & 0xffffffffu);
            if (l >= 6 && l < T2 + 6) g_mi[g] = mi;

            float x[6];
            x[0] = P[g * 3];     x[1] = P[g * 3 + 1];  x[2] = P[g * 3 + 2];
            x[3] = C[mi * 3];    x[4] = C[mi * 3 + 1]; x[5] = C[mi * 3 + 2];

            float a[32];
#pragma unroll
            for (int o = 0; o < 32; o++) {
                float acc = pb1[o];
#pragma unroll
                for (int i2 = 0; i2 < 6; i2++) acc = fmaf(__ldg(&pw1[o * 6 + i2]), x[i2], acc);
                a[o] = fmaxf(acc, 0.f);
            }
            float h[16];
#pragma unroll
            for (int o = 0; o < 16; o++) {
                float acc = pb2[o];
#pragma unroll
                for (int i2 = 0; i2 < 32; i2++) acc = fmaf(__ldg(&pw2[o * 32 + i2]), a[i2], acc);
                h[o] = fmaxf(acc, 0.f);
            }
            float z = pb3[0];
#pragma unroll
            for (int i2 = 0; i2 < 16; i2++) z = fmaf(__ldg(&pw3[i2]), h[i2], z);
            float w = 1.f / (1.f + expf(-z));

            f0 = w * x[0] + (1.f - w) * x[3];
            f1 = w * x[1] + (1.f - w) * x[4];
            f2 = w * x[2] + (1.f - w) * x[5];
        }
        fs[0][l] = f0; fs[1][l] = f1; fs[2][l] = f2;
    }
    __syncthreads();

    // conv1: 3->32, K=5, relu. outputs l in [2, T2+10)
    for (int idx = threadIdx.x; idx < 32 * (T2 + 8); idx += blockDim.x) {
        int co = idx / (T2 + 8);
        int l = idx % (T2 + 8) + 2;
        int g = t0 - 6 + l;
        float v = 0.f;
        if (g >= 0 && g < N) {
            float acc = bb1[co];
#pragma unroll
            for (int ci = 0; ci < 3; ci++)
#pragma unroll
                for (int k = 0; k < 5; k++)
                    acc = fmaf(__ldg(&bw1[(co * 3 + ci) * 5 + k]), fs[ci][l - 2 + k], acc);
            v = fmaxf(acc, 0.f);
        }
        h1[co][l] = v;
    }
    __syncthreads();

    // conv2: 32->32, K=5, relu. outputs l in [4, T2+8)
    for (int idx = threadIdx.x; idx < 32 * (T2 + 4); idx += blockDim.x) {
        int co = idx / (T2 + 4);
        int l = idx % (T2 + 4) + 4;
        int g = t0 - 6 + l;
        float v = 0.f;
        if (g >= 0 && g < N) {
            float acc = bb2[co];
#pragma unroll
            for (int ci = 0; ci < 32; ci++) {
                const float* wp = &bw2[(co * 32 + ci) * 5];
                const float* hp = &h1[ci][l - 2];
                acc = fmaf(__ldg(&wp[0]), hp[0], acc);
                acc = fmaf(__ldg(&wp[1]), hp[1], acc);
                acc = fmaf(__ldg(&wp[2]), hp[2], acc);
                acc = fmaf(__ldg(&wp[3]), hp[3], acc);
                acc = fmaf(__ldg(&wp[4]), hp[4], acc);
            }
            v = fmaxf(acc, 0.f);
        }
        h2[co][l] = v;
    }
    __syncthreads();

    // conv3: 32->3, K=5. outputs l in [6, T2+6) -> g in [t0, t0+T2)
    for (int idx = threadIdx.x; idx < 3 * T2; idx += blockDim.x) {
        int co = idx / T2;
        int l = idx % T2 + 6;
        int g = t0 - 6 + l;
        float acc = bb3[co];
#pragma unroll
        for (int ci = 0; ci < 32; ci++) {
            const float* wp = &bw3[(co * 32 + ci) * 5];
            const float* hp = &h2[ci][l - 2];
            acc = fmaf(__ldg(&wp[0]), hp[0], acc);
            acc = fmaf(__ldg(&wp[1]), hp[1], acc);
            acc = fmaf(__ldg(&wp[2]), hp[2], acc);
            acc = fmaf(__ldg(&wp[3]), hp[3], acc);
            acc = fmaf(__ldg(&wp[4]), hp[4], acc);
        }
        g_SM[g * 3 + co] = acc;
    }
}

// -------- K3: scatter (last-wins) + write S[step], copy SM -> S[step-1]. 1 block --------
__global__ __launch_bounds__(1024) void k_scatter(const float* __restrict__ C, int step) {
    int base = step * N;  // monotone across steps within one call; k_init resets g_best
    for (int n = threadIdx.x; n < N; n += blockDim.x)
        atomicMax(&g_best[g_mi[n]], base + n);
    __syncthreads();  // block-scope barrier orders global atomics before reads

    for (int j = threadIdx.x; j < N; j += blockDim.x) {
        int v = __ldcg(&g_best[j]);  // L2 read (atomics resolved at L2)
        float o0, o1, o2;
        if (v >= base) {
            int n = v - base;
            o0 = g_SM[n * 3]; o1 = g_SM[n * 3 + 1]; o2 = g_SM[n * 3 + 2];
        } else {
            o0 = C[j * 3]; o1 = C[j * 3 + 1]; o2 = C[j * 3 + 2];
        }
        g_S[step][j * 3] = o0; g_S[step][j * 3 + 1] = o1; g_S[step][j * 3 + 2] = o2;
    }
    for (int n = threadIdx.x; n < N * 3; n += blockDim.x)
        g_S[step - 1][n] = g_SM[n];
}

// -------- merge: fade-weighted gather (<=2 chunks per output position) --------
__global__ void k_merge(float* __restrict__ out) {
    int t = blockIdx.x * blockDim.x + threadIdx.x;
    if (t >= TOTAL) return;
    float a0 = 0.f, a1 = 0.f, a2 = 0.f, ws = 0.f;
#pragma unroll
    for (int k = 0; k < NUM_CHUNKS; k++) {
        int off = t - k * STRIDE;
        if (off >= 0 && off < N) {
            float w = 1.f;
            if (off < FADE)           w = 0.1f + (float)off * (0.9f / 1227.f);
            else if (off >= N - FADE) w = 1.0f - (float)(off - (N - FADE)) * (0.9f / 1227.f);
            a0 = fmaf(g_S[k][off * 3], w, a0);
            a1 = fmaf(g_S[k][off * 3 + 1], w, a1);
            a2 = fmaf(g_S[k][off * 3 + 2], w, a2);
            ws += w;
        }
    }
    float inv = 1.f / fmaxf(ws, 1e-8f);
    out[t * 3] = a0 * inv;
    out[t * 3 + 1] = a1 * inv;
    out[t * 3 + 2] = a2 * inv;
}

extern "C" void kernel_launch(void* const* d_in, const int* in_sizes, int n_in,
                              void* d_out, int out_size) {
    const float* chunks = (const float*)d_in[0];
    const float* bw1 = (const float*)d_in[1];  const float* bb1 = (const float*)d_in[2];
    const float* bw2 = (const float*)d_in[3];  const float* bb2 = (const float*)d_in[4];
    const float* bw3 = (const float*)d_in[5];  const float* bb3 = (const float*)d_in[6];
    const float* pw1 = (const float*)d_in[7];  const float* pb1 = (const float*)d_in[8];
    const float* pw2 = (const float*)d_in[9];  const float* pb2 = (const float*)d_in[10];
    const float* pw3 = (const float*)d_in[11]; const float* pb3 = (const float*)d_in[12];

    k_init<<<(N * 3 + 255) / 256, 256>>>(chunks);
    for (int i = 1; i < NUM_CHUNKS; i++) {
        const float* Ci = chunks + (size_t)i * N * 3;
        k_argmin<<<dim3(N / 256, NSEG), 256>>>(Ci, i);
        k_fuse_conv<<<N / T2, 256>>>(Ci, i, bw1, bb1, bw2, bb2, bw3, bb3,
                                     pw1, pb1, pw2, pb2, pw3, pb3);
        k_scatter<<<1, 1024>>>(Ci, i);
    }
    k_merge<<<(TOTAL + 255) / 256, 256>>>((float*)d_out);
}

// round 5
// speedup vs baseline: 1.9511x; 1.9511x over previous
#include <cuda_runtime.h>
#include <cuda_bf16.h>
#include <math.h>

#define N 8192
#define NSEG 32
#define SEG 256
#define T2 128
#define NUM_CHUNKS 8
#define STRIDE 6144
#define TOTAL 51200
#define FADE 1228

// -------- device scratch (no allocations allowed) --------
__device__ float g_S[NUM_CHUNKS][N * 3];          // smoothed chunks
__device__ float g_SM[N * 3];                     // sm output of current step
__device__ unsigned long long g_pkey[NSEG * N];   // partial argmin keys
__device__ int g_best[N];                         // scatter last-wins (monotone across steps)

// -------- init: S[0] = chunks[0], best = -1 (reset EVERY call: determinism) ----
__global__ void k_init(const float* __restrict__ chunks) {
    int i = blockIdx.x * blockDim.x + threadIdx.x;
    if (i < N * 3) g_S[0][i] = chunks[i];
    if (i < N) g_best[i] = -1;
}

// -------- K1: partial argmin, d2 rounding bit-identical to reference --------
// d2 = (pp + cc) - 2*dot; pp/cc separately-rounded squares l2r; dot = ascending
// FMA chain from 0. DO NOT CHANGE THE MATH (locked by round-4 pass).
// 4 independent accumulators break the serial min-chain; merge is exact
// first-occurrence (min value, tie -> min index).
__global__ __launch_bounds__(256) void k_argmin(const float* __restrict__ C, int step) {
    __shared__ float4 sc[SEG];   // {cx, cy, cz, cc}
    const float* P = g_S[step - 1];
    int seg = blockIdx.y;

    {
        int gj = seg * SEG + threadIdx.x;   // SEG == blockDim.x
        float cx = C[gj * 3], cy = C[gj * 3 + 1], cz = C[gj * 3 + 2];
        float cc = __fadd_rn(__fadd_rn(__fmul_rn(cx, cx), __fmul_rn(cy, cy)),
                             __fmul_rn(cz, cz));
        sc[threadIdx.x] = make_float4(cx, cy, cz, cc);
    }
    __syncthreads();

    int p = blockIdx.x * blockDim.x + threadIdx.x;
    float px = P[p * 3], py = P[p * 3 + 1], pz = P[p * 3 + 2];
    float pp = __fadd_rn(__fadd_rn(__fmul_rn(px, px), __fmul_rn(py, py)),
                         __fmul_rn(pz, pz));

    const float INF = __int_as_float(0x7f800000);
    float b0 = INF, b1 = INF, b2 = INF, b3 = INF;
    int i0 = 0, i1 = 1, i2 = 2, i3 = 3;

#pragma unroll 8
    for (int j = 0; j < SEG; j += 4) {
        float4 c0 = sc[j], c1 = sc[j + 1], c2 = sc[j + 2], c3 = sc[j + 3];
        float d0 = __fsub_rn(__fadd_rn(pp, c0.w),
                   __fmul_rn(2.0f, __fmaf_rn(pz, c0.z, __fmaf_rn(py, c0.y, __fmaf_rn(px, c0.x, 0.0f)))));
        float d1 = __fsub_rn(__fadd_rn(pp, c1.w),
                   __fmul_rn(2.0f, __fmaf_rn(pz, c1.z, __fmaf_rn(py, c1.y, __fmaf_rn(px, c1.x, 0.0f)))));
        float d2v = __fsub_rn(__fadd_rn(pp, c2.w),
                   __fmul_rn(2.0f, __fmaf_rn(pz, c2.z, __fmaf_rn(py, c2.y, __fmaf_rn(px, c2.x, 0.0f)))));
        float d3 = __fsub_rn(__fadd_rn(pp, c3.w),
                   __fmul_rn(2.0f, __fmaf_rn(pz, c3.z, __fmaf_rn(py, c3.y, __fmaf_rn(px, c3.x, 0.0f)))));
        if (d0 < b0) { b0 = d0; i0 = j; }       // strict <: first occurrence in class
        if (d1 < b1) { b1 = d1; i1 = j + 1; }
        if (d2v < b2) { b2 = d2v; i2 = j + 2; }
        if (d3 < b3) { b3 = d3; i3 = j + 3; }
    }

    // exact merge: min value; on equal value, min index
    if (b1 < b0 || (b1 == b0 && i1 < i0)) { b0 = b1; i0 = i1; }
    if (b3 < b2 || (b3 == b2 && i3 < i2)) { b2 = b3; i2 = i3; }
    if (b2 < b0 || (b2 == b0 && i2 < i0)) { b0 = b2; i0 = i2; }

    unsigned int b = __float_as_uint(b0);
    b = (b & 0x80000000u) ? ~b : (b | 0x80000000u);  // order-preserving transform
    g_pkey[seg * N + p] =
        ((unsigned long long)b << 32) | (unsigned int)(seg * SEG + i0);
}

// -------- K2: reduce argmin + scatter-atomic + fused (MLP mix) + 3 convs ------
__global__ __launch_bounds__(256) void k_fuse_conv(
    const float* __restrict__ C, int step,
    const float* __restrict__ bw1, const float* __restrict__ bb1,
    const float* __restrict__ bw2, const float* __restrict__ bb2,
    const float* __restrict__ bw3, const float* __restrict__ bb3,
    const float* __restrict__ pw1, const float* __restrict__ pb1,
    const float* __restrict__ pw2, const float* __restrict__ pb2,
    const float* __restrict__ pw3, const float* __restrict__ pb3) {
    __shared__ float fs[3][T2 + 12];
    __shared__ float h1[32][T2 + 12];
    __shared__ float h2[32][T2 + 12];

    int t0 = blockIdx.x * T2;
    const float* P = g_S[step - 1];
    int base = step * N;

    // phase 0: reduce partial argmin keys, scatter-atomic, compute fused
    for (int l = threadIdx.x; l < T2 + 12; l += blockDim.x) {
        int g = t0 - 6 + l;
        float f0 = 0.f, f1 = 0.f, f2 = 0.f;
        if (g >= 0 && g < N) {
            unsigned long long k = g_pkey[g];
#pragma unroll
            for (int s = 1; s < NSEG; s++) {
                unsigned long long v = g_pkey[s * N + g];
                if (v < k) k = v;
            }
            int mi = (int)(unsigned int)(k & 0xffffffffu);
            if (l >= 6 && l < T2 + 6)
                atomicMax(&g_best[mi], base + g);   // last-wins scatter winner

            float x[6];
            x[0] = P[g * 3];     x[1] = P[g * 3 + 1];  x[2] = P[g * 3 + 2];
            x[3] = C[mi * 3];    x[4] = C[mi * 3 + 1]; x[5] = C[mi * 3 + 2];

            float a[32];
#pragma unroll
            for (int o = 0; o < 32; o++) {
                float acc = pb1[o];
#pragma unroll
                for (int i2 = 0; i2 < 6; i2++) acc = fmaf(__ldg(&pw1[o * 6 + i2]), x[i2], acc);
                a[o] = fmaxf(acc, 0.f);
            }
            float h[16];
#pragma unroll
            for (int o = 0; o < 16; o++) {
                float acc = pb2[o];
#pragma unroll
                for (int i2 = 0; i2 < 32; i2++) acc = fmaf(__ldg(&pw2[o * 32 + i2]), a[i2], acc);
                h[o] = fmaxf(acc, 0.f);
            }
            float z = pb3[0];
#pragma unroll
            for (int i2 = 0; i2 < 16; i2++) z = fmaf(__ldg(&pw3[i2]), h[i2], z);
            float w = 1.f / (1.f + expf(-z));

            f0 = w * x[0] + (1.f - w) * x[3];
            f1 = w * x[1] + (1.f - w) * x[4];
            f2 = w * x[2] + (1.f - w) * x[5];
        }
        fs[0][l] = f0; fs[1][l] = f1; fs[2][l] = f2;
    }
    __syncthreads();

    // conv1: 3->32, K=5, relu. outputs l in [2, T2+10)
    for (int idx = threadIdx.x; idx < 32 * (T2 + 8); idx += blockDim.x) {
        int co = idx / (T2 + 8);
        int l = idx % (T2 + 8) + 2;
        int g = t0 - 6 + l;
        float v = 0.f;
        if (g >= 0 && g < N) {
            float acc = bb1[co];
#pragma unroll
            for (int ci = 0; ci < 3; ci++)
#pragma unroll
                for (int k = 0; k < 5; k++)
                    acc = fmaf(__ldg(&bw1[(co * 3 + ci) * 5 + k]), fs[ci][l - 2 + k], acc);
            v = fmaxf(acc, 0.f);
        }
        h1[co][l] = v;
    }
    __syncthreads();

    // conv2: 32->32, K=5, relu. outputs l in [4, T2+8)
    for (int idx = threadIdx.x; idx < 32 * (T2 + 4); idx += blockDim.x) {
        int co = idx / (T2 + 4);
        int l = idx % (T2 + 4) + 4;
        int g = t0 - 6 + l;
        float v = 0.f;
        if (g >= 0 && g < N) {
            float acc = bb2[co];
#pragma unroll
            for (int ci = 0; ci < 32; ci++) {
                const float* wp = &bw2[(co * 32 + ci) * 5];
                const float* hp = &h1[ci][l - 2];
                acc = fmaf(__ldg(&wp[0]), hp[0], acc);
                acc = fmaf(__ldg(&wp[1]), hp[1], acc);
                acc = fmaf(__ldg(&wp[2]), hp[2], acc);
                acc = fmaf(__ldg(&wp[3]), hp[3], acc);
                acc = fmaf(__ldg(&wp[4]), hp[4], acc);
            }
            v = fmaxf(acc, 0.f);
        }
        h2[co][l] = v;
    }
    __syncthreads();

    // conv3: 32->3, K=5. outputs l in [6, T2+6) -> g in [t0, t0+T2)
    for (int idx = threadIdx.x; idx < 3 * T2; idx += blockDim.x) {
        int co = idx / T2;
        int l = idx % T2 + 6;
        int g = t0 - 6 + l;
        float acc = bb3[co];
#pragma unroll
        for (int ci = 0; ci < 32; ci++) {
            const float* wp = &bw3[(co * 32 + ci) * 5];
            const float* hp = &h2[ci][l - 2];
            acc = fmaf(__ldg(&wp[0]), hp[0], acc);
            acc = fmaf(__ldg(&wp[1]), hp[1], acc);
            acc = fmaf(__ldg(&wp[2]), hp[2], acc);
            acc = fmaf(__ldg(&wp[3]), hp[3], acc);
            acc = fmaf(__ldg(&wp[4]), hp[4], acc);
        }
        g_SM[g * 3 + co] = acc;
    }
}

// -------- K3: multi-block gather: S[step] from best/SM/C; copy SM->S[step-1] --
__global__ __launch_bounds__(512) void k_scatter_b(const float* __restrict__ C, int step) {
    int base = step * N;
    int j = blockIdx.x * blockDim.x + threadIdx.x;   // 16*512 = 8192
    int v = g_best[j];
    float o0, o1, o2;
    if (v >= base) {
        int n = v - base;
        o0 = g_SM[n * 3]; o1 = g_SM[n * 3 + 1]; o2 = g_SM[n * 3 + 2];
    } else {
        o0 = C[j * 3]; o1 = C[j * 3 + 1]; o2 = C[j * 3 + 2];
    }
    g_S[step][j * 3] = o0; g_S[step][j * 3 + 1] = o1; g_S[step][j * 3 + 2] = o2;
    // copy SM -> S[step-1] (3 elements per thread, coalesced)
    float* dst = g_S[step - 1];
    int t = blockIdx.x * blockDim.x * 3 + threadIdx.x;
#pragma unroll
    for (int r = 0; r < 3; r++) { dst[t] = g_SM[t]; t += blockDim.x; }
}

// -------- merge: fade-weighted gather (<=2 chunks per output position) --------
__global__ void k_merge(float* __restrict__ out) {
    int t = blockIdx.x * blockDim.x + threadIdx.x;
    if (t >= TOTAL) return;
    float a0 = 0.f, a1 = 0.f, a2 = 0.f, ws = 0.f;
#pragma unroll
    for (int k = 0; k < NUM_CHUNKS; k++) {
        int off = t - k * STRIDE;
        if (off >= 0 && off < N) {
            float w = 1.f;
            if (off < FADE)           w = 0.1f + (float)off * (0.9f / 1227.f);
            else if (off >= N - FADE) w = 1.0f - (float)(off - (N - FADE)) * (0.9f / 1227.f);
            a0 = fmaf(g_S[k][off * 3], w, a0);
            a1 = fmaf(g_S[k][off * 3 + 1], w, a1);
            a2 = fmaf(g_S[k][off * 3 + 2], w, a2);
            ws += w;
        }
    }
    float inv = 1.f / fmaxf(ws, 1e-8f);
    out[t * 3] = a0 * inv;
    out[t * 3 + 1] = a1 * inv;
    out[t * 3 + 2] = a2 * inv;
}

extern "C" void kernel_launch(void* const* d_in, const int* in_sizes, int n_in,
                              void* d_out, int out_size) {
    const float* chunks = (const float*)d_in[0];
    const float* bw1 = (const float*)d_in[1];  const float* bb1 = (const float*)d_in[2];
    const float* bw2 = (const float*)d_in[3];  const float* bb2 = (const float*)d_in[4];
    const float* bw3 = (const float*)d_in[5];  const float* bb3 = (const float*)d_in[6];
    const float* pw1 = (const float*)d_in[7];  const float* pb1 = (const float*)d_in[8];
    const float* pw2 = (const float*)d_in[9];  const float* pb2 = (const float*)d_in[10];
    const float* pw3 = (const float*)d_in[11]; const float* pb3 = (const float*)d_in[12];

    k_init<<<(N * 3 + 255) / 256, 256>>>(chunks);
    for (int i = 1; i < NUM_CHUNKS; i++) {
        const float* Ci = chunks + (size_t)i * N * 3;
        k_argmin<<<dim3(N / 256, NSEG), 256>>>(Ci, i);
        k_fuse_conv<<<N / T2, 256>>>(Ci, i, bw1, bb1, bw2, bb2, bw3, bb3,
                                     pw1, pb1, pw2, pb2, pw3, pb3);
        k_scatter_b<<<N / 512, 512>>>(Ci, i);
    }
    k_merge<<<(TOTAL + 255) / 256, 256>>>((float*)d_out);
}

// round 6
// speedup vs baseline: 2.0436x; 1.0474x over previous
#include <cuda_runtime.h>
#include <cuda_bf16.h>
#include <math.h>

#define N 8192
#define NSEG 32
#define SEG 256
#define T2 128
#define NUM_CHUNKS 8
#define STRIDE 6144
#define TOTAL 51200
#define FADE 1228
#define GRID 148
#define BLK 256

// -------- device scratch (no allocations allowed) --------
__device__ float g_S[NUM_CHUNKS][N * 3];          // smoothed chunks
__device__ float g_SM[N * 3];                     // sm output of current step
__device__ unsigned long long g_pkey[NSEG * N];   // partial argmin keys
__device__ int g_best[N];                         // scatter last-wins (monotone base)
__device__ int g_ticket;                          // grid barrier (monotone forever)

// ---- ticket grid barrier: barrier k owns tickets [kG,(k+1)G); no reset ever ----
__device__ __forceinline__ void gsync() {
    __syncthreads();
    if (threadIdx.x == 0) {
        __threadfence();
        int t = atomicAdd(&g_ticket, 1);
        int target = (t / GRID + 1) * GRID;
        int cur;
        do {
            asm volatile("ld.acquire.gpu.global.b32 %0, [%1];"
                         : "=r"(cur) : "l"(&g_ticket));
        } while (cur < target);
    }
    __syncthreads();
}

__global__ __launch_bounds__(BLK, 1) void k_persist(
    const float* __restrict__ chunks, float* __restrict__ out,
    const float* __restrict__ bw1, const float* __restrict__ bb1,
    const float* __restrict__ bw2, const float* __restrict__ bb2,
    const float* __restrict__ bw3, const float* __restrict__ bb3,
    const float* __restrict__ pw1, const float* __restrict__ pb1,
    const float* __restrict__ pw2, const float* __restrict__ pb2,
    const float* __restrict__ pw3, const float* __restrict__ pb3) {

    __shared__ union {
        float4 sc[SEG];
        struct { float fs[3][T2 + 12]; float h1[32][T2 + 12]; float h2[32][T2 + 12]; } cv;
    } sm;

    // reset g_best (ordered before step-1 phase-B atomics by the A->B barrier)
    for (int j = blockIdx.x * BLK + threadIdx.x; j < N; j += GRID * BLK)
        g_best[j] = -1;

    for (int step = 1; step < NUM_CHUNKS; step++) {
        const float* C = chunks + (size_t)step * N * 3;
        const float* P = (step == 1) ? chunks : g_S[step - 1];
        int base = step * N;

        // ============ phase A: partial argmin (1024 virtual blocks) ============
        // d2 = (pp + cc) - 2*dot; dot = ascending FMA chain from 0.
        // MATH LOCKED (bit-identical to passing R4/R5 kernels).
        for (int v = blockIdx.x; v < 32 * NSEG; v += GRID) {
            int pt = v & 31, seg = v >> 5;
            {
                int gj = seg * SEG + threadIdx.x;
                float cx = C[gj * 3], cy = C[gj * 3 + 1], cz = C[gj * 3 + 2];
                float cc = __fadd_rn(__fadd_rn(__fmul_rn(cx, cx), __fmul_rn(cy, cy)),
                                     __fmul_rn(cz, cz));
                sm.sc[threadIdx.x] = make_float4(cx, cy, cz, cc);
            }
            __syncthreads();

            int p = pt * BLK + threadIdx.x;
            float px = P[p * 3], py = P[p * 3 + 1], pz = P[p * 3 + 2];
            float pp = __fadd_rn(__fadd_rn(__fmul_rn(px, px), __fmul_rn(py, py)),
                                 __fmul_rn(pz, pz));

            const float INF = __int_as_float(0x7f800000);
            float b0 = INF, b1 = INF, b2 = INF, b3 = INF;
            int i0 = 0, i1 = 1, i2 = 2, i3 = 3;

#pragma unroll 8
            for (int j = 0; j < SEG; j += 4) {
                float4 c0 = sm.sc[j], c1 = sm.sc[j + 1], c2 = sm.sc[j + 2], c3 = sm.sc[j + 3];
                float d0 = __fsub_rn(__fadd_rn(pp, c0.w),
                           __fmul_rn(2.0f, __fmaf_rn(pz, c0.z, __fmaf_rn(py, c0.y, __fmaf_rn(px, c0.x, 0.0f)))));
                float d1 = __fsub_rn(__fadd_rn(pp, c1.w),
                           __fmul_rn(2.0f, __fmaf_rn(pz, c1.z, __fmaf_rn(py, c1.y, __fmaf_rn(px, c1.x, 0.0f)))));
                float d2v = __fsub_rn(__fadd_rn(pp, c2.w),
                           __fmul_rn(2.0f, __fmaf_rn(pz, c2.z, __fmaf_rn(py, c2.y, __fmaf_rn(px, c2.x, 0.0f)))));
                float d3 = __fsub_rn(__fadd_rn(pp, c3.w),
                           __fmul_rn(2.0f, __fmaf_rn(pz, c3.z, __fmaf_rn(py, c3.y, __fmaf_rn(px, c3.x, 0.0f)))));
                if (d0 < b0) { b0 = d0; i0 = j; }
                if (d1 < b1) { b1 = d1; i1 = j + 1; }
                if (d2v < b2) { b2 = d2v; i2 = j + 2; }
                if (d3 < b3) { b3 = d3; i3 = j + 3; }
            }
            if (b1 < b0 || (b1 == b0 && i1 < i0)) { b0 = b1; i0 = i1; }
            if (b3 < b2 || (b3 == b2 && i3 < i2)) { b2 = b3; i2 = i3; }
            if (b2 < b0 || (b2 == b0 && i2 < i0)) { b0 = b2; i0 = i2; }

            unsigned int b = __float_as_uint(b0);
            b = (b & 0x80000000u) ? ~b : (b | 0x80000000u);
            g_pkey[seg * N + p] =
                ((unsigned long long)b << 32) | (unsigned int)(seg * SEG + i0);
            __syncthreads();
        }
        gsync();

        // ============ phase B: reduce + scatter-atomic + MLP + 3 convs ==========
        for (int tile = blockIdx.x; tile < N / T2; tile += GRID) {
            int t0 = tile * T2;

            for (int l = threadIdx.x; l < T2 + 12; l += BLK) {
                int g = t0 - 6 + l;
                float f0 = 0.f, f1 = 0.f, f2 = 0.f;
                if (g >= 0 && g < N) {
                    unsigned long long k = g_pkey[g];
#pragma unroll
                    for (int s = 1; s < NSEG; s++) {
                        unsigned long long vv = g_pkey[s * N + g];
                        if (vv < k) k = vv;
                    }
                    int mi = (int)(unsigned int)(k & 0xffffffffu);
                    if (l >= 6 && l < T2 + 6)
                        atomicMax(&g_best[mi], base + g);   // last-wins winner

                    float x[6];
                    x[0] = P[g * 3];     x[1] = P[g * 3 + 1];  x[2] = P[g * 3 + 2];
                    x[3] = C[mi * 3];    x[4] = C[mi * 3 + 1]; x[5] = C[mi * 3 + 2];

                    float a[32];
#pragma unroll
                    for (int o = 0; o < 32; o++) {
                        float acc = pb1[o];
#pragma unroll
                        for (int q = 0; q < 6; q++) acc = fmaf(__ldg(&pw1[o * 6 + q]), x[q], acc);
                        a[o] = fmaxf(acc, 0.f);
                    }
                    float h[16];
#pragma unroll
                    for (int o = 0; o < 16; o++) {
                        float acc = pb2[o];
#pragma unroll
                        for (int q = 0; q < 32; q++) acc = fmaf(__ldg(&pw2[o * 32 + q]), a[q], acc);
                        h[o] = fmaxf(acc, 0.f);
                    }
                    float z = pb3[0];
#pragma unroll
                    for (int q = 0; q < 16; q++) z = fmaf(__ldg(&pw3[q]), h[q], z);
                    float w = 1.f / (1.f + expf(-z));

                    f0 = w * x[0] + (1.f - w) * x[3];
                    f1 = w * x[1] + (1.f - w) * x[4];
                    f2 = w * x[2] + (1.f - w) * x[5];
                }
                sm.cv.fs[0][l] = f0; sm.cv.fs[1][l] = f1; sm.cv.fs[2][l] = f2;
            }
            __syncthreads();

            for (int idx = threadIdx.x; idx < 32 * (T2 + 8); idx += BLK) {
                int co = idx / (T2 + 8);
                int l = idx % (T2 + 8) + 2;
                int g = t0 - 6 + l;
                float vo = 0.f;
                if (g >= 0 && g < N) {
                    float acc = bb1[co];
#pragma unroll
                    for (int ci = 0; ci < 3; ci++)
#pragma unroll
                        for (int k = 0; k < 5; k++)
                            acc = fmaf(__ldg(&bw1[(co * 3 + ci) * 5 + k]), sm.cv.fs[ci][l - 2 + k], acc);
                    vo = fmaxf(acc, 0.f);
                }
                sm.cv.h1[co][l] = vo;
            }
            __syncthreads();

            for (int idx = threadIdx.x; idx < 32 * (T2 + 4); idx += BLK) {
                int co = idx / (T2 + 4);
                int l = idx % (T2 + 4) + 4;
                int g = t0 - 6 + l;
                float vo = 0.f;
                if (g >= 0 && g < N) {
                    float acc = bb2[co];
#pragma unroll
                    for (int ci = 0; ci < 32; ci++) {
                        const float* wp = &bw2[(co * 32 + ci) * 5];
                        const float* hp = &sm.cv.h1[ci][l - 2];
                        acc = fmaf(__ldg(&wp[0]), hp[0], acc);
                        acc = fmaf(__ldg(&wp[1]), hp[1], acc);
                        acc = fmaf(__ldg(&wp[2]), hp[2], acc);
                        acc = fmaf(__ldg(&wp[3]), hp[3], acc);
                        acc = fmaf(__ldg(&wp[4]), hp[4], acc);
                    }
                    vo = fmaxf(acc, 0.f);
                }
                sm.cv.h2[co][l] = vo;
            }
            __syncthreads();

            for (int idx = threadIdx.x; idx < 3 * T2; idx += BLK) {
                int co = idx / T2;
                int l = idx % T2 + 6;
                int g = t0 - 6 + l;
                float acc = bb3[co];
#pragma unroll
                for (int ci = 0; ci < 32; ci++) {
                    const float* wp = &bw3[(co * 32 + ci) * 5];
                    const float* hp = &sm.cv.h2[ci][l - 2];
                    acc = fmaf(__ldg(&wp[0]), hp[0], acc);
                    acc = fmaf(__ldg(&wp[1]), hp[1], acc);
                    acc = fmaf(__ldg(&wp[2]), hp[2], acc);
                    acc = fmaf(__ldg(&wp[3]), hp[3], acc);
                    acc = fmaf(__ldg(&wp[4]), hp[4], acc);
                }
                g_SM[g * 3 + co] = acc;
            }
            __syncthreads();
        }
        gsync();

        // ============ phase C: gather S[step] + copy SM -> S[step-1] ============
        for (int j = blockIdx.x * BLK + threadIdx.x; j < N; j += GRID * BLK) {
            int v = g_best[j];
            float o0, o1, o2;
            if (v >= base) {
                int n = v - base;
                o0 = g_SM[n * 3]; o1 = g_SM[n * 3 + 1]; o2 = g_SM[n * 3 + 2];
            } else {
                o0 = C[j * 3]; o1 = C[j * 3 + 1]; o2 = C[j * 3 + 2];
            }
            g_S[step][j * 3] = o0; g_S[step][j * 3 + 1] = o1; g_S[step][j * 3 + 2] = o2;
        }
        {
            float* dst = g_S[step - 1];
            for (int t = blockIdx.x * BLK + threadIdx.x; t < N * 3; t += GRID * BLK)
                dst[t] = g_SM[t];
        }
        gsync();
    }

    // ============ merge: fade-weighted gather ============
    for (int t = blockIdx.x * BLK + threadIdx.x; t < TOTAL; t += GRID * BLK) {
        float a0 = 0.f, a1 = 0.f, a2 = 0.f, ws = 0.f;
#pragma unroll
        for (int k = 0; k < NUM_CHUNKS; k++) {
            int off = t - k * STRIDE;
            if (off >= 0 && off < N) {
                float w = 1.f;
                if (off < FADE)           w = 0.1f + (float)off * (0.9f / 1227.f);
                else if (off >= N - FADE) w = 1.0f - (float)(off - (N - FADE)) * (0.9f / 1227.f);
                a0 = fmaf(g_S[k][off * 3], w, a0);
                a1 = fmaf(g_S[k][off * 3 + 1], w, a1);
                a2 = fmaf(g_S[k][off * 3 + 2], w, a2);
                ws += w;
            }
        }
        float inv = 1.f / fmaxf(ws, 1e-8f);
        out[t * 3] = a0 * inv;
        out[t * 3 + 1] = a1 * inv;
        out[t * 3 + 2] = a2 * inv;
    }
}

extern "C" void kernel_launch(void* const* d_in, const int* in_sizes, int n_in,
                              void* d_out, int out_size) {
    const float* chunks = (const float*)d_in[0];
    const float* bw1 = (const float*)d_in[1];  const float* bb1 = (const float*)d_in[2];
    const float* bw2 = (const float*)d_in[3];  const float* bb2 = (const float*)d_in[4];
    const float* bw3 = (const float*)d_in[5];  const float* bb3 = (const float*)d_in[6];
    const float* pw1 = (const float*)d_in[7];  const float* pb1 = (const float*)d_in[8];
    const float* pw2 = (const float*)d_in[9];  const float* pb2 = (const float*)d_in[10];
    const float* pw3 = (const float*)d_in[11]; const float* pb3 = (const float*)d_in[12];

    k_persist<<<GRID, BLK>>>(chunks, (float*)d_out,
                             bw1, bb1, bw2, bb2, bw3, bb3,
                             pw1, pb1, pw2, pb2, pw3, pb3);
}

// round 7
// speedup vs baseline: 2.0874x; 1.0214x over previous
#include <cuda_runtime.h>
#include <cuda_bf16.h>
#include <math.h>

#define N 8192
#define SEG 128
#define NSEGV (N / SEG)          // 64
#define T2 128
#define NUM_CHUNKS 8
#define STRIDE 6144
#define TOTAL 51200
#define FADE 1228
#define GRID 148
#define BLK 512
#define PTILES (N / BLK)         // 16
#define NVIRT (PTILES * NSEGV)   // 1024

// -------- device scratch (no allocations allowed) --------
__device__ float g_S[NUM_CHUNKS][N * 3];          // smoothed chunks
__device__ float g_SM[N * 3];                     // sm output of current step
__device__ unsigned long long g_key[N];           // argmin keys (atomicMin)
__device__ int g_best[N];                         // scatter last-wins (monotone base)
__device__ int g_ticket;                          // grid barrier (monotone forever)

// ---- ticket grid barrier: barrier k owns tickets [kG,(k+1)G); no reset ever ----
__device__ __forceinline__ void gsync() {
    __syncthreads();
    if (threadIdx.x == 0) {
        __threadfence();
        int t = atomicAdd(&g_ticket, 1);
        int target = (t / GRID + 1) * GRID;
        int cur;
        do {
            asm volatile("ld.acquire.gpu.global.b32 %0, [%1];"
                         : "=r"(cur) : "l"(&g_ticket));
        } while (cur < target);
    }
    __syncthreads();
}

__global__ __launch_bounds__(BLK, 1) void k_persist(
    const float* __restrict__ chunks, float* __restrict__ out,
    const float* __restrict__ bw1, const float* __restrict__ bb1,
    const float* __restrict__ bw2, const float* __restrict__ bb2,
    const float* __restrict__ bw3, const float* __restrict__ bb3,
    const float* __restrict__ pw1, const float* __restrict__ pb1,
    const float* __restrict__ pw2, const float* __restrict__ pb2,
    const float* __restrict__ pw3, const float* __restrict__ pb3) {

    __shared__ union {
        float4 sc[SEG];
        struct { float fs[3][T2 + 12]; float h1[32][T2 + 12]; float h2[32][T2 + 12]; } cv;
    } sm;

    // reset g_best and g_key; must be globally visible before step-1 phase A
    for (int j = blockIdx.x * BLK + threadIdx.x; j < N; j += GRID * BLK) {
        g_best[j] = -1;
        g_key[j] = 0xFFFFFFFFFFFFFFFFull;
    }
    gsync();

    for (int step = 1; step < NUM_CHUNKS; step++) {
        const float* C = chunks + (size_t)step * N * 3;
        const float* P = (step == 1) ? chunks : g_S[step - 1];
        int base = step * N;

        // ============ phase A: argmin via atomicMin on packed keys ============
        // d2 = (pp + cc) - 2*dot; dot = ascending FMA chain from 0; final op
        // fused as fma(-2,dot,s) which is bit-identical (2*dot exact).
        // MATH LOCKED (bit-identical ordering to passing R4/R5 kernels).
        for (int v = blockIdx.x; v < NVIRT; v += GRID) {
            int pt = v & (PTILES - 1), seg = v >> 4;
            if (threadIdx.x < SEG) {
                int gj = seg * SEG + threadIdx.x;
                float cx = C[gj * 3], cy = C[gj * 3 + 1], cz = C[gj * 3 + 2];
                float cc = __fadd_rn(__fadd_rn(__fmul_rn(cx, cx), __fmul_rn(cy, cy)),
                                     __fmul_rn(cz, cz));
                sm.sc[threadIdx.x] = make_float4(cx, cy, cz, cc);
            }
            __syncthreads();

            int p = pt * BLK + threadIdx.x;
            float px = P[p * 3], py = P[p * 3 + 1], pz = P[p * 3 + 2];
            float pp = __fadd_rn(__fadd_rn(__fmul_rn(px, px), __fmul_rn(py, py)),
                                 __fmul_rn(pz, pz));

            const float INF = __int_as_float(0x7f800000);
            float b0 = INF, b1 = INF, b2 = INF, b3 = INF;
            int i0 = 0, i1 = 1, i2 = 2, i3 = 3;

#pragma unroll 4
            for (int j = 0; j < SEG; j += 4) {
                float4 c0 = sm.sc[j], c1 = sm.sc[j + 1], c2 = sm.sc[j + 2], c3 = sm.sc[j + 3];
                float s0 = __fadd_rn(pp, c0.w);
                float s1 = __fadd_rn(pp, c1.w);
                float s2 = __fadd_rn(pp, c2.w);
                float s3 = __fadd_rn(pp, c3.w);
                float d0 = __fmaf_rn(-2.0f,
                    __fmaf_rn(pz, c0.z, __fmaf_rn(py, c0.y, __fmaf_rn(px, c0.x, 0.0f))), s0);
                float d1 = __fmaf_rn(-2.0f,
                    __fmaf_rn(pz, c1.z, __fmaf_rn(py, c1.y, __fmaf_rn(px, c1.x, 0.0f))), s1);
                float d2v = __fmaf_rn(-2.0f,
                    __fmaf_rn(pz, c2.z, __fmaf_rn(py, c2.y, __fmaf_rn(px, c2.x, 0.0f))), s2);
                float d3 = __fmaf_rn(-2.0f,
                    __fmaf_rn(pz, c3.z, __fmaf_rn(py, c3.y, __fmaf_rn(px, c3.x, 0.0f))), s3);
                if (d0 < b0) { b0 = d0; i0 = j; }       // strict <: first occurrence
                if (d1 < b1) { b1 = d1; i1 = j + 1; }
                if (d2v < b2) { b2 = d2v; i2 = j + 2; }
                if (d3 < b3) { b3 = d3; i3 = j + 3; }
            }
            // exact merge: min value; on equal value, min index
            if (b1 < b0 || (b1 == b0 && i1 < i0)) { b0 = b1; i0 = i1; }
            if (b3 < b2 || (b3 == b2 && i3 < i2)) { b2 = b3; i2 = i3; }
            if (b2 < b0 || (b2 == b0 && i2 < i0)) { b0 = b2; i0 = i2; }

            unsigned int b = __float_as_uint(b0);
            b = (b & 0x80000000u) ? ~b : (b | 0x80000000u);  // order-preserving
            unsigned long long key =
                ((unsigned long long)b << 32) | (unsigned int)(seg * SEG + i0);
            atomicMin(&g_key[p], key);   // min value, tie -> min index (exact)
            __syncthreads();
        }
        gsync();

        // ============ phase B: scatter-atomic + MLP + 3 convs ==========
        for (int tile = blockIdx.x; tile < N / T2; tile += GRID) {
            int t0 = tile * T2;

            for (int l = threadIdx.x; l < T2 + 12; l += BLK) {
                int g = t0 - 6 + l;
                float f0 = 0.f, f1 = 0.f, f2 = 0.f;
                if (g >= 0 && g < N) {
                    int mi = (int)(unsigned int)(g_key[g] & 0xffffffffu);
                    if (l >= 6 && l < T2 + 6)
                        atomicMax(&g_best[mi], base + g);   // last-wins winner

                    float x[6];
                    x[0] = P[g * 3];     x[1] = P[g * 3 + 1];  x[2] = P[g * 3 + 2];
                    x[3] = C[mi * 3];    x[4] = C[mi * 3 + 1]; x[5] = C[mi * 3 + 2];

                    float a[32];
#pragma unroll
                    for (int o = 0; o < 32; o++) {
                        float acc = pb1[o];
#pragma unroll
                        for (int q = 0; q < 6; q++) acc = fmaf(__ldg(&pw1[o * 6 + q]), x[q], acc);
                        a[o] = fmaxf(acc, 0.f);
                    }
                    float h[16];
#pragma unroll
                    for (int o = 0; o < 16; o++) {
                        float acc = pb2[o];
#pragma unroll
                        for (int q = 0; q < 32; q++) acc = fmaf(__ldg(&pw2[o * 32 + q]), a[q], acc);
                        h[o] = fmaxf(acc, 0.f);
                    }
                    float z = pb3[0];
#pragma unroll
                    for (int q = 0; q < 16; q++) z = fmaf(__ldg(&pw3[q]), h[q], z);
                    float w = 1.f / (1.f + expf(-z));

                    f0 = w * x[0] + (1.f - w) * x[3];
                    f1 = w * x[1] + (1.f - w) * x[4];
                    f2 = w * x[2] + (1.f - w) * x[5];
                }
                sm.cv.fs[0][l] = f0; sm.cv.fs[1][l] = f1; sm.cv.fs[2][l] = f2;
            }
            __syncthreads();

            for (int idx = threadIdx.x; idx < 32 * (T2 + 8); idx += BLK) {
                int co = idx / (T2 + 8);
                int l = idx % (T2 + 8) + 2;
                int g = t0 - 6 + l;
                float vo = 0.f;
                if (g >= 0 && g < N) {
                    float acc = bb1[co];
#pragma unroll
                    for (int ci = 0; ci < 3; ci++)
#pragma unroll
                        for (int k = 0; k < 5; k++)
                            acc = fmaf(__ldg(&bw1[(co * 3 + ci) * 5 + k]), sm.cv.fs[ci][l - 2 + k], acc);
                    vo = fmaxf(acc, 0.f);
                }
                sm.cv.h1[co][l] = vo;
            }
            __syncthreads();

            for (int idx = threadIdx.x; idx < 32 * (T2 + 4); idx += BLK) {
                int co = idx / (T2 + 4);
                int l = idx % (T2 + 4) + 4;
                int g = t0 - 6 + l;
                float vo = 0.f;
                if (g >= 0 && g < N) {
                    float acc = bb2[co];
#pragma unroll
                    for (int ci = 0; ci < 32; ci++) {
                        const float* wp = &bw2[(co * 32 + ci) * 5];
                        const float* hp = &sm.cv.h1[ci][l - 2];
                        acc = fmaf(__ldg(&wp[0]), hp[0], acc);
                        acc = fmaf(__ldg(&wp[1]), hp[1], acc);
                        acc = fmaf(__ldg(&wp[2]), hp[2], acc);
                        acc = fmaf(__ldg(&wp[3]), hp[3], acc);
                        acc = fmaf(__ldg(&wp[4]), hp[4], acc);
                    }
                    vo = fmaxf(acc, 0.f);
                }
                sm.cv.h2[co][l] = vo;
            }
            __syncthreads();

            for (int idx = threadIdx.x; idx < 3 * T2; idx += BLK) {
                int co = idx / T2;
                int l = idx % T2 + 6;
                int g = t0 - 6 + l;
                float acc = bb3[co];
#pragma unroll
                for (int ci = 0; ci < 32; ci++) {
                    const float* wp = &bw3[(co * 32 + ci) * 5];
                    const float* hp = &sm.cv.h2[ci][l - 2];
                    acc = fmaf(__ldg(&wp[0]), hp[0], acc);
                    acc = fmaf(__ldg(&wp[1]), hp[1], acc);
                    acc = fmaf(__ldg(&wp[2]), hp[2], acc);
                    acc = fmaf(__ldg(&wp[3]), hp[3], acc);
                    acc = fmaf(__ldg(&wp[4]), hp[4], acc);
                }
                g_SM[g * 3 + co] = acc;
            }
            __syncthreads();
        }
        gsync();

        // ==== phase C: gather S[step]; copy SM -> S[step-1]; re-init keys ====
        for (int j = blockIdx.x * BLK + threadIdx.x; j < N; j += GRID * BLK) {
            int v = g_best[j];
            float o0, o1, o2;
            if (v >= base) {
                int n = v - base;
                o0 = g_SM[n * 3]; o1 = g_SM[n * 3 + 1]; o2 = g_SM[n * 3 + 2];
            } else {
                o0 = C[j * 3]; o1 = C[j * 3 + 1]; o2 = C[j * 3 + 2];
            }
            g_S[step][j * 3] = o0; g_S[step][j * 3 + 1] = o1; g_S[step][j * 3 + 2] = o2;
            g_key[j] = 0xFFFFFFFFFFFFFFFFull;   // ready for next step's phase A
        }
        {
            float* dst = g_S[step - 1];
            for (int t = blockIdx.x * BLK + threadIdx.x; t < N * 3; t += GRID * BLK)
                dst[t] = g_SM[t];
        }
        gsync();
    }

    // ============ merge: fade-weighted gather ============
    for (int t = blockIdx.x * BLK + threadIdx.x; t < TOTAL; t += GRID * BLK) {
        float a0 = 0.f, a1 = 0.f, a2 = 0.f, ws = 0.f;
#pragma unroll
        for (int k = 0; k < NUM_CHUNKS; k++) {
            int off = t - k * STRIDE;
            if (off >= 0 && off < N) {
                float w = 1.f;
                if (off < FADE)           w = 0.1f + (float)off * (0.9f / 1227.f);
                else if (off >= N - FADE) w = 1.0f - (float)(off - (N - FADE)) * (0.9f / 1227.f);
                a0 = fmaf(g_S[k][off * 3], w, a0);
                a1 = fmaf(g_S[k][off * 3 + 1], w, a1);
                a2 = fmaf(g_S[k][off * 3 + 2], w, a2);
                ws += w;
            }
        }
        float inv = 1.f / fmaxf(ws, 1e-8f);
        out[t * 3] = a0 * inv;
        out[t * 3 + 1] = a1 * inv;
        out[t * 3 + 2] = a2 * inv;
    }
}

extern "C" void kernel_launch(void* const* d_in, const int* in_sizes, int n_in,
                              void* d_out, int out_size) {
    const float* chunks = (const float*)d_in[0];
    const float* bw1 = (const float*)d_in[1];  const float* bb1 = (const float*)d_in[2];
    const float* bw2 = (const float*)d_in[3];  const float* bb2 = (const float*)d_in[4];
    const float* bw3 = (const float*)d_in[5];  const float* bb3 = (const float*)d_in[6];
    const float* pw1 = (const float*)d_in[7];  const float* pb1 = (const float*)d_in[8];
    const float* pw2 = (const float*)d_in[9];  const float* pb2 = (const float*)d_in[10];
    const float* pw3 = (const float*)d_in[11]; const float* pb3 = (const float*)d_in[12];

    k_persist<<<GRID, BLK>>>(chunks, (float*)d_out,
                             bw1, bb1, bw2, bb2, bw3, bb3,
                             pw1, pb1, pw2, pb2, pw3, pb3);
}

// round 10
// speedup vs baseline: 2.1364x; 1.0235x over previous
#include <cuda_runtime.h>
#include <cuda_bf16.h>
#include <math.h>

#define N 8192
#define T2 128
#define NUM_CHUNKS 8
#define STRIDE 6144
#define TOTAL 51200
#define FADE 1228
#define GRID 148
#define BLK 512
#define PREG 4
#define PT_N 4                    // N / (BLK*PREG)
#define SEGA 32
#define NSEGA (N / SEGA)          // 256
#define NVIRT (PT_N * NSEGA)      // 1024

// -------- device scratch (no allocations allowed) --------
__device__ float g_S[NUM_CHUNKS][N * 3];          // smoothed chunks
__device__ float g_SM[N * 3];                     // sm output of current step
__device__ unsigned long long g_key[N];           // argmin keys (atomicMin)
__device__ int g_best[N];                         // scatter last-wins (monotone base)
__device__ int g_ticket;                          // grid barrier (monotone forever)

// ---- ticket grid barrier: barrier k owns tickets [kG,(k+1)G); no reset ever ----
__device__ __forceinline__ void gsync() {
    __syncthreads();
    if (threadIdx.x == 0) {
        __threadfence();
        int t = atomicAdd(&g_ticket, 1);
        int target = (t / GRID + 1) * GRID;
        int cur;
        do {
            asm volatile("ld.acquire.gpu.global.b32 %0, [%1];"
                         : "=r"(cur) : "l"(&g_ticket));
        } while (cur < target);
    }
    __syncthreads();
}

__global__ __launch_bounds__(BLK, 1) void k_persist(
    const float* __restrict__ chunks, float* __restrict__ out,
    const float* __restrict__ bw1, const float* __restrict__ bb1,
    const float* __restrict__ bw2, const float* __restrict__ bb2,
    const float* __restrict__ bw3, const float* __restrict__ bb3,
    const float* __restrict__ pw1, const float* __restrict__ pb1,
    const float* __restrict__ pw2, const float* __restrict__ pb2,
    const float* __restrict__ pw3, const float* __restrict__ pb3) {

    __shared__ union {
        float4 buf[2][SEGA];                       // phase A double buffer (1 KB)
        struct { float fs[3][T2 + 12]; float h1[32][T2 + 12]; float h2[32][T2 + 12]; } cv;
    } sm;

    // reset g_best / g_key; must be globally visible before step-1 phase A
    for (int j = blockIdx.x * BLK + threadIdx.x; j < N; j += GRID * BLK) {
        g_best[j] = -1;
        g_key[j] = 0xFFFFFFFFFFFFFFFFull;
    }
    gsync();

    const int tid = threadIdx.x;
    const int pt = blockIdx.x & (PT_N - 1);   // GRID % 4 == 0 -> invariant per block

    for (int step = 1; step < NUM_CHUNKS; step++) {
        const float* C = chunks + (size_t)step * N * 3;
        const float* P = (step == 1) ? chunks : g_S[step - 1];
        int base = step * N;

        // ============ phase A: argmin, 4 p per thread, double-buffered c ============
        // d2 = fma(-2, dot, pp+cc); dot = ascending FMA chain from 0.
        // MATH LOCKED — bit-identical to the passing R4-R7 kernels.
        {
            float px[PREG], py[PREG], pz[PREG], pp[PREG];
#pragma unroll
            for (int k = 0; k < PREG; k++) {
                int p = pt * (BLK * PREG) + k * BLK + tid;
                float x = P[p * 3], y = P[p * 3 + 1], z = P[p * 3 + 2];
                px[k] = x; py[k] = y; pz[k] = z;
                pp[k] = __fadd_rn(__fadd_rn(__fmul_rn(x, x), __fmul_rn(y, y)),
                                  __fmul_rn(z, z));
            }

            int v = blockIdx.x;
            float ncx = 0.f, ncy = 0.f, ncz = 0.f;
            if (v < NVIRT && tid < SEGA) {
                int gj = (v >> 2) * SEGA + tid;
                ncx = C[gj * 3]; ncy = C[gj * 3 + 1]; ncz = C[gj * 3 + 2];
            }
            int par = 0;
            const float INF = __int_as_float(0x7f800000);

            for (; v < NVIRT; v += GRID) {
                if (tid < SEGA) {
                    float cc = __fadd_rn(__fadd_rn(__fmul_rn(ncx, ncx), __fmul_rn(ncy, ncy)),
                                         __fmul_rn(ncz, ncz));
                    sm.buf[par][tid] = make_float4(ncx, ncy, ncz, cc);
                }
                __syncthreads();
                int vn = v + GRID;
                if (vn < NVIRT && tid < SEGA) {      // prefetch next tile's c
                    int gj = (vn >> 2) * SEGA + tid;
                    ncx = C[gj * 3]; ncy = C[gj * 3 + 1]; ncz = C[gj * 3 + 2];
                }

                int seg = v >> 2;
                float b0[PREG], b1[PREG];
                int i0[PREG], i1[PREG];
#pragma unroll
                for (int k = 0; k < PREG; k++) { b0[k] = INF; b1[k] = INF; i0[k] = 0; i1[k] = 1; }

#pragma unroll
                for (int j = 0; j < SEGA; j += 2) {
                    float4 c0 = sm.buf[par][j], c1 = sm.buf[par][j + 1];
#pragma unroll
                    for (int k = 0; k < PREG; k++) {
                        float d0 = __fmaf_rn(-2.0f,
                            __fmaf_rn(pz[k], c0.z, __fmaf_rn(py[k], c0.y, __fmaf_rn(px[k], c0.x, 0.0f))),
                            __fadd_rn(pp[k], c0.w));
                        float d1 = __fmaf_rn(-2.0f,
                            __fmaf_rn(pz[k], c1.z, __fmaf_rn(py[k], c1.y, __fmaf_rn(px[k], c1.x, 0.0f))),
                            __fadd_rn(pp[k], c1.w));
                        if (d0 < b0[k]) { b0[k] = d0; i0[k] = j; }      // strict <: first occurrence
                        if (d1 < b1[k]) { b1[k] = d1; i1[k] = j + 1; }
                    }
                }

#pragma unroll
                for (int k = 0; k < PREG; k++) {
                    float bb = b0[k]; int ii = i0[k];
                    if (b1[k] < bb || (b1[k] == bb && i1[k] < ii)) { bb = b1[k]; ii = i1[k]; }
                    unsigned int ob = __float_as_uint(bb);
                    ob = (ob & 0x80000000u) ? ~ob : (ob | 0x80000000u);  // order-preserving
                    unsigned long long key =
                        ((unsigned long long)ob << 32) | (unsigned int)(seg * SEGA + ii);
                    atomicMin(&g_key[pt * (BLK * PREG) + k * BLK + tid], key);
                }
                par ^= 1;
                // no trailing sync: double buffer + the top-of-loop sync make it safe
            }
        }
        gsync();

        // ============ phase B: scatter-atomic + MLP + 3 convs ==========
        for (int tile = blockIdx.x; tile < N / T2; tile += GRID) {
            int t0 = tile * T2;

            for (int l = tid; l < T2 + 12; l += BLK) {
                int g = t0 - 6 + l;
                float f0 = 0.f, f1 = 0.f, f2 = 0.f;
                if (g >= 0 && g < N) {
                    int mi = (int)(unsigned int)(g_key[g] & 0xffffffffu);
                    if (l >= 6 && l < T2 + 6)
                        atomicMax(&g_best[mi], base + g);   // last-wins winner

                    float x[6];
                    x[0] = P[g * 3];     x[1] = P[g * 3 + 1];  x[2] = P[g * 3 + 2];
                    x[3] = C[mi * 3];    x[4] = C[mi * 3 + 1]; x[5] = C[mi * 3 + 2];

                    float a[32];
#pragma unroll
                    for (int o = 0; o < 32; o++) {
                        float acc = pb1[o];
#pragma unroll
                        for (int q = 0; q < 6; q++) acc = fmaf(__ldg(&pw1[o * 6 + q]), x[q], acc);
                        a[o] = fmaxf(acc, 0.f);
                    }
                    float h[16];
#pragma unroll
                    for (int o = 0; o < 16; o++) {
                        float acc = pb2[o];
#pragma unroll
                        for (int q = 0; q < 32; q++) acc = fmaf(__ldg(&pw2[o * 32 + q]), a[q], acc);
                        h[o] = fmaxf(acc, 0.f);
                    }
                    float z = pb3[0];
#pragma unroll
                    for (int q = 0; q < 16; q++) z = fmaf(__ldg(&pw3[q]), h[q], z);
                    float w = 1.f / (1.f + expf(-z));

                    f0 = w * x[0] + (1.f - w) * x[3];
                    f1 = w * x[1] + (1.f - w) * x[4];
                    f2 = w * x[2] + (1.f - w) * x[5];
                }
                sm.cv.fs[0][l] = f0; sm.cv.fs[1][l] = f1; sm.cv.fs[2][l] = f2;
            }
            __syncthreads();

            for (int idx = tid; idx < 32 * (T2 + 8); idx += BLK) {
                int co = idx / (T2 + 8);
                int l = idx % (T2 + 8) + 2;
                int g = t0 - 6 + l;
                float vo = 0.f;
                if (g >= 0 && g < N) {
                    float acc = bb1[co];
#pragma unroll
                    for (int ci = 0; ci < 3; ci++)
#pragma unroll
                        for (int k = 0; k < 5; k++)
                            acc = fmaf(__ldg(&bw1[(co * 3 + ci) * 5 + k]), sm.cv.fs[ci][l - 2 + k], acc);
                    vo = fmaxf(acc, 0.f);
                }
                sm.cv.h1[co][l] = vo;
            }
            __syncthreads();

            for (int idx = tid; idx < 32 * (T2 + 4); idx += BLK) {
                int co = idx / (T2 + 4);
                int l = idx % (T2 + 4) + 4;
                int g = t0 - 6 + l;
                float vo = 0.f;
                if (g >= 0 && g < N) {
                    float acc = bb2[co];
#pragma unroll
                    for (int ci = 0; ci < 32; ci++) {
                        const float* wp = &bw2[(co * 32 + ci) * 5];
                        const float* hp = &sm.cv.h1[ci][l - 2];
                        acc = fmaf(__ldg(&wp[0]), hp[0], acc);
                        acc = fmaf(__ldg(&wp[1]), hp[1], acc);
                        acc = fmaf(__ldg(&wp[2]), hp[2], acc);
                        acc = fmaf(__ldg(&wp[3]), hp[3], acc);
                        acc = fmaf(__ldg(&wp[4]), hp[4], acc);
                    }
                    vo = fmaxf(acc, 0.f);
                }
                sm.cv.h2[co][l] = vo;
            }
            __syncthreads();

            for (int idx = tid; idx < 3 * T2; idx += BLK) {
                int co = idx / T2;
                int l = idx % T2 + 6;
                int g = t0 - 6 + l;
                float acc = bb3[co];
#pragma unroll
                for (int ci = 0; ci < 32; ci++) {
                    const float* wp = &bw3[(co * 32 + ci) * 5];
                    const float* hp = &sm.cv.h2[ci][l - 2];
                    acc = fmaf(__ldg(&wp[0]), hp[0], acc);
                    acc = fmaf(__ldg(&wp[1]), hp[1], acc);
                    acc = fmaf(__ldg(&wp[2]), hp[2], acc);
                    acc = fmaf(__ldg(&wp[3]), hp[3], acc);
                    acc = fmaf(__ldg(&wp[4]), hp[4], acc);
                }
                g_SM[g * 3 + co] = acc;
            }
            __syncthreads();
        }
        gsync();

        // ==== phase C: gather S[step]; copy SM -> S[step-1]; re-init keys ====
        for (int j = blockIdx.x * BLK + tid; j < N; j += GRID * BLK) {
            int v = g_best[j];
            float o0, o1, o2;
            if (v >= base) {
                int n = v - base;
                o0 = g_SM[n * 3]; o1 = g_SM[n * 3 + 1]; o2 = g_SM[n * 3 + 2];
            } else {
                o0 = C[j * 3]; o1 = C[j * 3 + 1]; o2 = C[j * 3 + 2];
            }
            g_S[step][j * 3] = o0; g_S[step][j * 3 + 1] = o1; g_S[step][j * 3 + 2] = o2;
            g_key[j] = 0xFFFFFFFFFFFFFFFFull;   // ready for next step's phase A
        }
        {
            float* dst = g_S[step - 1];
            for (int t = blockIdx.x * BLK + tid; t < N * 3; t += GRID * BLK)
                dst[t] = g_SM[t];
        }
        gsync();
    }

    // ============ merge: fade-weighted gather ============
    for (int t = blockIdx.x * BLK + tid; t < TOTAL; t += GRID * BLK) {
        float a0 = 0.f, a1 = 0.f, a2 = 0.f, ws = 0.f;
#pragma unroll
        for (int k = 0; k < NUM_CHUNKS; k++) {
            int off = t - k * STRIDE;
            if (off >= 0 && off < N) {
                float w = 1.f;
                if (off < FADE)           w = 0.1f + (float)off * (0.9f / 1227.f);
                else if (off >= N - FADE) w = 1.0f - (float)(off - (N - FADE)) * (0.9f / 1227.f);
                a0 = fmaf(g_S[k][off * 3], w, a0);
                a1 = fmaf(g_S[k][off * 3 + 1], w, a1);
                a2 = fmaf(g_S[k][off * 3 + 2], w, a2);
                ws += w;
            }
        }
        float inv = 1.f / fmaxf(ws, 1e-8f);
        out[t * 3] = a0 * inv;
        out[t * 3 + 1] = a1 * inv;
        out[t * 3 + 2] = a2 * inv;
    }
}

extern "C" void kernel_launch(void* const* d_in, const int* in_sizes, int n_in,
                              void* d_out, int out_size) {
    const float* chunks = (const float*)d_in[0];
    const float* bw1 = (const float*)d_in[1];  const float* bb1 = (const float*)d_in[2];
    const float* bw2 = (const float*)d_in[3];  const float* bb2 = (const float*)d_in[4];
    const float* bw3 = (const float*)d_in[5];  const float* bb3 = (const float*)d_in[6];
    const float* pw1 = (const float*)d_in[7];  const float* pb1 = (const float*)d_in[8];
    const float* pw2 = (const float*)d_in[9];  const float* pb2 = (const float*)d_in[10];
    const float* pw3 = (const float*)d_in[11]; const float* pb3 = (const float*)d_in[12];

    k_persist<<<GRID, BLK>>>(chunks, (float*)d_out,
                             bw1, bb1, bw2, bb2, bw3, bb3,
                             pw1, pb1, pw2, pb2, pw3, pb3);
}